// round 2
// baseline (speedup 1.0000x reference)
#include <cuda_runtime.h>

#define NN 100000
#define NE 1600000
#define DD 128
#define NP 500000

// ---- scratch (device globals; no allocation allowed) ----
__device__ __align__(16) float g_x[NN * DD];      // layer input / final h
__device__ __align__(16) float g_h[NN * DD];      // layer1 output
__device__ __align__(16) float g_xnorm[NN * DD];
__device__ __align__(16) float g_agg[NN * DD];
__device__ int g_deg_s[NN];
__device__ int g_deg_r[NN];
__device__ int g_rowstart[NN + 1];
__device__ int g_cursor[NN];
__device__ int g_esrc[NE];

__device__ __forceinline__ float4 f4add(float4 a, float4 b) {
    return make_float4(a.x + b.x, a.y + b.y, a.z + b.z, a.w + b.w);
}

// packed f32x2 fma: d = a*b + d  (Blackwell sm_103a; 2 lanes/op, rt=2 -> 2x FFMA rate)
__device__ __forceinline__ void ffma2(unsigned long long& d,
                                      unsigned long long a,
                                      unsigned long long b) {
    asm("fma.rn.f32x2 %0, %1, %2, %0;" : "+l"(d) : "l"(a), "l"(b));
}
__device__ __forceinline__ float f2lo(unsigned long long p) {
    return __uint_as_float((unsigned)p);
}
__device__ __forceinline__ float f2hi(unsigned long long p) {
    return __uint_as_float((unsigned)(p >> 32));
}
__device__ __forceinline__ unsigned long long fdup(float w) {
    unsigned u = __float_as_uint(w);
    return (unsigned long long)u | ((unsigned long long)u << 32);
}

// ---------------------------------------------------------------------------
__global__ void k_init_deg() {
    int i = blockIdx.x * blockDim.x + threadIdx.x;
    if (i < NN) { g_deg_s[i] = 1; g_deg_r[i] = 1; }   // self-loop counts
}

__global__ void k_count(const int* __restrict__ senders, const int* __restrict__ receivers) {
    int stride = gridDim.x * blockDim.x;
    for (int e = blockIdx.x * blockDim.x + threadIdx.x; e < NE; e += stride) {
        atomicAdd(&g_deg_s[senders[e]], 1);
        atomicAdd(&g_deg_r[receivers[e]], 1);
    }
}

// single-block exclusive scan of in-degrees (excluding self-loop) -> rowstart/cursor
__global__ void k_scan() {
    __shared__ int ss[1024];
    int t = threadIdx.x;
    const int chunk = (NN + 1023) / 1024;
    int beg = t * chunk;
    int end = beg + chunk; if (end > NN) end = NN;
    int s = 0;
    for (int i = beg; i < end; i++) s += g_deg_r[i] - 1;
    ss[t] = s;
    __syncthreads();
    for (int off = 1; off < 1024; off <<= 1) {
        int v = (t >= off) ? ss[t - off] : 0;
        __syncthreads();
        ss[t] += v;
        __syncthreads();
    }
    int run = (t == 0) ? 0 : ss[t - 1];
    for (int i = beg; i < end; i++) {
        g_rowstart[i] = run;
        g_cursor[i] = run;
        run += g_deg_r[i] - 1;
    }
    if (t == 0) g_rowstart[NN] = ss[1023];
}

__global__ void k_scatter(const int* __restrict__ senders, const int* __restrict__ receivers) {
    int stride = gridDim.x * blockDim.x;
    for (int e = blockIdx.x * blockDim.x + threadIdx.x; e < NE; e += stride) {
        int r = receivers[e];
        int pos = atomicAdd(&g_cursor[r], 1);
        g_esrc[pos] = senders[e];
    }
}

// gather x0 = emb[node_ids] AND xnorm = x0 * rsqrt(deg_s) in one pass
__global__ void k_gather_norm(const int* __restrict__ node_ids, const float* __restrict__ emb) {
    int i = blockIdx.x * blockDim.x + threadIdx.x;
    if (i < NN * (DD / 4)) {
        int node = i >> 5;
        int q = i & 31;
        int src = node_ids[node];
        float4 v = ((const float4*)emb)[src * 32 + q];
        ((float4*)g_x)[i] = v;
        float sc = rsqrtf((float)g_deg_s[node]);
        v.x *= sc; v.y *= sc; v.z *= sc; v.w *= sc;
        ((float4*)g_xnorm)[i] = v;
    }
}

// one warp per node: acc = xnorm[self] + sum_{in-edges} xnorm[src]; scale cnt^-1.5
__global__ void k_aggregate() {
    int gw = (blockIdx.x * blockDim.x + threadIdx.x) >> 5;
    if (gw >= NN) return;
    int lane = threadIdx.x & 31;
    const float4* __restrict__ xn = (const float4*)g_xnorm;
    float4 acc = xn[gw * 32 + lane];     // self-loop message
    int s = g_rowstart[gw], e = g_rowstart[gw + 1];
    int j = s;
    for (; j + 8 <= e; j += 8) {
        int s0 = g_esrc[j], s1 = g_esrc[j + 1], s2 = g_esrc[j + 2], s3 = g_esrc[j + 3];
        int s4 = g_esrc[j + 4], s5 = g_esrc[j + 5], s6 = g_esrc[j + 6], s7 = g_esrc[j + 7];
        float4 a0 = xn[s0 * 32 + lane];
        float4 a1 = xn[s1 * 32 + lane];
        float4 a2 = xn[s2 * 32 + lane];
        float4 a3 = xn[s3 * 32 + lane];
        float4 a4 = xn[s4 * 32 + lane];
        float4 a5 = xn[s5 * 32 + lane];
        float4 a6 = xn[s6 * 32 + lane];
        float4 a7 = xn[s7 * 32 + lane];
        acc = f4add(acc, f4add(f4add(f4add(a0, a1), f4add(a2, a3)),
                               f4add(f4add(a4, a5), f4add(a6, a7))));
    }
    for (; j < e; j++) acc = f4add(acc, xn[g_esrc[j] * 32 + lane]);
    float cnt = (float)(e - s + 1);
    float sc = rsqrtf(cnt) / cnt;        // cnt^-1.5
    acc.x *= sc; acc.y *= sc; acc.z *= sc; acc.w *= sc;
    ((float4*)g_agg)[gw * 32 + lane] = acc;
}

// C[row] = act( [X|A][row] @ W[256x128] + b ).  BM=64, BN=128, BK=16.
// f32x2 packed over M-pairs; B columns stored duplicated in smem.
// Optionally also writes XN[row] = act(...) * rsqrt(deg[row]).
template <bool RELU, bool WRITE_XNORM>
__global__ void __launch_bounds__(256) k_gemm(
    const float* __restrict__ X, const float* __restrict__ A,
    const float* __restrict__ W, const float* __restrict__ b,
    float* __restrict__ C, float* __restrict__ XN,
    const int* __restrict__ deg, int M)
{
    __shared__ float As[16][64];
    __shared__ unsigned long long Bsd[16][128];
    int tid = threadIdx.x;
    int tx = tid & 31;          // column group
    int ty = tid >> 5;          // row group (8 rows)
    int block_row = blockIdx.x * 64;

    unsigned long long acc[4][4];
#pragma unroll
    for (int mp = 0; mp < 4; mp++)
#pragma unroll
        for (int nc = 0; nc < 4; nc++) acc[mp][nc] = 0ULL;

    int ar = tid >> 2, aq = tid & 3;
    int arow = block_row + ar;
    int arow_c = arow < M ? arow : M - 1;

    for (int kb = 0; kb < 256; kb += 16) {
        const float* src = (kb < 128) ? X : A;
        int koff = kb & 127;
        float4 av = ((const float4*)(src + arow_c * DD + koff))[aq];
        As[aq * 4 + 0][ar] = av.x;
        As[aq * 4 + 1][ar] = av.y;
        As[aq * 4 + 2][ar] = av.z;
        As[aq * 4 + 3][ar] = av.w;
#pragma unroll
        for (int l = 0; l < 2; l++) {
            int kk = (tid >> 5) + l * 8;
            int c0 = (tid & 31) * 4;
            float4 wv = ((const float4*)(W + (kb + kk) * DD + c0))[0];
            Bsd[kk][c0 + 0] = fdup(wv.x);
            Bsd[kk][c0 + 1] = fdup(wv.y);
            Bsd[kk][c0 + 2] = fdup(wv.z);
            Bsd[kk][c0 + 3] = fdup(wv.w);
        }
        __syncthreads();
#pragma unroll
        for (int kk = 0; kk < 16; kk++) {
            ulonglong2 a01 = *(const ulonglong2*)&As[kk][ty * 8];
            ulonglong2 a23 = *(const ulonglong2*)&As[kk][ty * 8 + 4];
            ulonglong2 b01 = *(const ulonglong2*)&Bsd[kk][2 * tx];
            ulonglong2 b23 = *(const ulonglong2*)&Bsd[kk][2 * tx + 64];
            unsigned long long aU[4] = {a01.x, a01.y, a23.x, a23.y};
            unsigned long long bU[4] = {b01.x, b01.y, b23.x, b23.y};
#pragma unroll
            for (int mp = 0; mp < 4; mp++)
#pragma unroll
                for (int nc = 0; nc < 4; nc++)
                    ffma2(acc[mp][nc], aU[mp], bU[nc]);
        }
        __syncthreads();
    }

    // cols handled: {2tx, 2tx+1, 64+2tx, 64+2tx+1}
    int c0 = 2 * tx, c2 = 64 + 2 * tx;
    float2 bA = *(const float2*)(b + c0);
    float2 bB = *(const float2*)(b + c2);
#pragma unroll
    for (int mp = 0; mp < 4; mp++) {
#pragma unroll
        for (int h = 0; h < 2; h++) {
            int row = block_row + ty * 8 + 2 * mp + h;
            if (row < M) {
                float v0 = (h ? f2hi(acc[mp][0]) : f2lo(acc[mp][0])) + bA.x;
                float v1 = (h ? f2hi(acc[mp][1]) : f2lo(acc[mp][1])) + bA.y;
                float v2 = (h ? f2hi(acc[mp][2]) : f2lo(acc[mp][2])) + bB.x;
                float v3 = (h ? f2hi(acc[mp][3]) : f2lo(acc[mp][3])) + bB.y;
                if (RELU) {
                    v0 = fmaxf(v0, 0.f); v1 = fmaxf(v1, 0.f);
                    v2 = fmaxf(v2, 0.f); v3 = fmaxf(v3, 0.f);
                }
                *(float2*)(C + row * DD + c0) = make_float2(v0, v1);
                *(float2*)(C + row * DD + c2) = make_float2(v2, v3);
                if (WRITE_XNORM) {
                    float sc = rsqrtf((float)deg[row]);
                    *(float2*)(XN + row * DD + c0) = make_float2(v0 * sc, v1 * sc);
                    *(float2*)(XN + row * DD + c2) = make_float2(v2 * sc, v3 * sc);
                }
            }
        }
    }
}

// link predictor: per pair p, z = h[a]*h[b]; score = relu(z@Wa+ba)@Wb + bb
__global__ void __launch_bounds__(256) k_linkpred(
    const float* __restrict__ H, const int* __restrict__ pairs,
    const float* __restrict__ Wa, const float* __restrict__ ba,
    const float* __restrict__ Wb, const float* __restrict__ bb,
    float* __restrict__ out)
{
    __shared__ float As[16][64];
    __shared__ unsigned long long Bsd[16][128];
    int tid = threadIdx.x;
    int tx = tid & 31;
    int ty = tid >> 5;
    int bp = blockIdx.x * 64;

    unsigned long long acc[4][4];
#pragma unroll
    for (int mp = 0; mp < 4; mp++)
#pragma unroll
        for (int nc = 0; nc < 4; nc++) acc[mp][nc] = 0ULL;

    int ar = tid >> 2, aq = tid & 3;
    int prow = bp + ar;
    int pc = prow < NP ? prow : NP - 1;
    int ia = pairs[2 * pc];
    int ib = pairs[2 * pc + 1];

    for (int kb = 0; kb < 128; kb += 16) {
        float4 ha = ((const float4*)(H + ia * DD + kb))[aq];
        float4 hb = ((const float4*)(H + ib * DD + kb))[aq];
        As[aq * 4 + 0][ar] = ha.x * hb.x;
        As[aq * 4 + 1][ar] = ha.y * hb.y;
        As[aq * 4 + 2][ar] = ha.z * hb.z;
        As[aq * 4 + 3][ar] = ha.w * hb.w;
#pragma unroll
        for (int l = 0; l < 2; l++) {
            int kk = (tid >> 5) + l * 8;
            int c0 = (tid & 31) * 4;
            float4 wv = ((const float4*)(Wa + (kb + kk) * DD + c0))[0];
            Bsd[kk][c0 + 0] = fdup(wv.x);
            Bsd[kk][c0 + 1] = fdup(wv.y);
            Bsd[kk][c0 + 2] = fdup(wv.z);
            Bsd[kk][c0 + 3] = fdup(wv.w);
        }
        __syncthreads();
#pragma unroll
        for (int kk = 0; kk < 16; kk++) {
            ulonglong2 a01 = *(const ulonglong2*)&As[kk][ty * 8];
            ulonglong2 a23 = *(const ulonglong2*)&As[kk][ty * 8 + 4];
            ulonglong2 b01 = *(const ulonglong2*)&Bsd[kk][2 * tx];
            ulonglong2 b23 = *(const ulonglong2*)&Bsd[kk][2 * tx + 64];
            unsigned long long aU[4] = {a01.x, a01.y, a23.x, a23.y};
            unsigned long long bU[4] = {b01.x, b01.y, b23.x, b23.y};
#pragma unroll
            for (int mp = 0; mp < 4; mp++)
#pragma unroll
                for (int nc = 0; nc < 4; nc++)
                    ffma2(acc[mp][nc], aU[mp], bU[nc]);
        }
        __syncthreads();
    }

    int c0 = 2 * tx, c2 = 64 + 2 * tx;
    float2 baA = *(const float2*)(ba + c0);
    float2 baB = *(const float2*)(ba + c2);
    float2 wbA = *(const float2*)(Wb + c0);
    float2 wbB = *(const float2*)(Wb + c2);
    float bbv = bb[0];
#pragma unroll
    for (int mp = 0; mp < 4; mp++) {
#pragma unroll
        for (int h = 0; h < 2; h++) {
            float v = fmaxf((h ? f2hi(acc[mp][0]) : f2lo(acc[mp][0])) + baA.x, 0.f) * wbA.x
                    + fmaxf((h ? f2hi(acc[mp][1]) : f2lo(acc[mp][1])) + baA.y, 0.f) * wbA.y
                    + fmaxf((h ? f2hi(acc[mp][2]) : f2lo(acc[mp][2])) + baB.x, 0.f) * wbB.x
                    + fmaxf((h ? f2hi(acc[mp][3]) : f2lo(acc[mp][3])) + baB.y, 0.f) * wbB.y;
#pragma unroll
            for (int off = 16; off > 0; off >>= 1)
                v += __shfl_xor_sync(0xffffffffu, v, off);
            if (tx == 0) {
                int row = bp + ty * 8 + 2 * mp + h;
                if (row < NP) out[row] = v + bbv;
            }
        }
    }
}

// ---------------------------------------------------------------------------
extern "C" void kernel_launch(void* const* d_in, const int* in_sizes, int n_in,
                              void* d_out, int out_size) {
    const int*   node_ids  = (const int*)d_in[0];
    const int*   senders   = (const int*)d_in[1];
    const int*   receivers = (const int*)d_in[2];
    const int*   pairs     = (const int*)d_in[3];
    const float* emb       = (const float*)d_in[4];
    const float* W1        = (const float*)d_in[5];
    const float* b1        = (const float*)d_in[6];
    const float* W2        = (const float*)d_in[7];
    const float* b2        = (const float*)d_in[8];
    const float* Wa        = (const float*)d_in[9];
    const float* ba        = (const float*)d_in[10];
    const float* Wb        = (const float*)d_in[11];
    const float* bb        = (const float*)d_in[12];
    float* out = (float*)d_out;

    float *x, *h, *ag, *xn;
    int* degs;
    cudaGetSymbolAddress((void**)&x,  g_x);
    cudaGetSymbolAddress((void**)&h,  g_h);
    cudaGetSymbolAddress((void**)&ag, g_agg);
    cudaGetSymbolAddress((void**)&xn, g_xnorm);
    cudaGetSymbolAddress((void**)&degs, g_deg_s);

    const int elem4 = NN * (DD / 4);
    const int vb = (elem4 + 255) / 256;

    k_init_deg<<<(NN + 255) / 256, 256>>>();
    k_count<<<2048, 256>>>(senders, receivers);
    k_scan<<<1, 1024>>>();
    k_scatter<<<2048, 256>>>(senders, receivers);
    k_gather_norm<<<vb, 256>>>(node_ids, emb);   // writes g_x + g_xnorm

    // layer 1: x -> h (relu); epilogue also writes xnorm for layer-2 aggregate
    k_aggregate<<<vb, 256>>>();
    k_gemm<true, true><<<(NN + 63) / 64, 256>>>(x, ag, W1, b1, h, xn, degs, NN);

    // layer 2: h -> x (no relu)
    k_aggregate<<<vb, 256>>>();
    k_gemm<false, false><<<(NN + 63) / 64, 256>>>(h, ag, W2, b2, x, nullptr, degs, NN);

    // link predictor
    k_linkpred<<<(NP + 63) / 64, 256>>>(x, pairs, Wa, ba, Wb, bb, out);
}

// round 4
// speedup vs baseline: 1.4216x; 1.4216x over previous
#include <cuda_runtime.h>
#include <cuda_bf16.h>
#include <cstdint>

#define NN 100000
#define NE 1600000
#define DD 128
#define NP 500000

// ---- scratch (device globals) ----
__device__ __align__(16) float g_x[NN * DD];
__device__ __align__(16) float g_h[NN * DD];
__device__ __align__(16) float g_xnorm[NN * DD];
__device__ __align__(16) float g_agg[NN * DD];
__device__ int g_deg_s[NN];
__device__ int g_deg_r[NN];
__device__ int g_rowstart[NN + 1];
__device__ int g_cursor[NN];
__device__ int g_esrc[NE];
// transposed, hi/lo-split weights: Wt[n][k] = W[k][n]
__device__ __align__(16) __nv_bfloat16 g_w1t_hi[DD * 256];
__device__ __align__(16) __nv_bfloat16 g_w1t_lo[DD * 256];
__device__ __align__(16) __nv_bfloat16 g_w2t_hi[DD * 256];
__device__ __align__(16) __nv_bfloat16 g_w2t_lo[DD * 256];
__device__ __align__(16) __nv_bfloat16 g_wat_hi[DD * DD];
__device__ __align__(16) __nv_bfloat16 g_wat_lo[DD * DD];

// ---- helpers ----
__device__ __forceinline__ uint32_t smem_u32(const void* p) {
    uint32_t a;
    asm("{.reg .u64 t; cvta.to.shared.u64 t, %1; cvt.u32.u64 %0, t;}" : "=r"(a) : "l"(p));
    return a;
}
#define LDSM_X4(r, a) \
    asm volatile("ldmatrix.sync.aligned.m8n8.x4.shared.b16 {%0,%1,%2,%3}, [%4];" \
        : "=r"((r)[0]), "=r"((r)[1]), "=r"((r)[2]), "=r"((r)[3]) : "r"(a))
#define LDSM_X2(r, a) \
    asm volatile("ldmatrix.sync.aligned.m8n8.x2.shared.b16 {%0,%1}, [%2];" \
        : "=r"((r)[0]), "=r"((r)[1]) : "r"(a))
__device__ __forceinline__ void hmma(float* d, const uint32_t* a, const uint32_t* b) {
    asm volatile(
        "mma.sync.aligned.m16n8k16.row.col.f32.bf16.bf16.f32 "
        "{%0,%1,%2,%3}, {%4,%5,%6,%7}, {%8,%9}, {%0,%1,%2,%3};"
        : "+f"(d[0]), "+f"(d[1]), "+f"(d[2]), "+f"(d[3])
        : "r"(a[0]), "r"(a[1]), "r"(a[2]), "r"(a[3]), "r"(b[0]), "r"(b[1]));
}
__device__ __forceinline__ uint32_t pack_hilo(float a, float b, uint32_t& lo_out) {
    __nv_bfloat16 ha = __float2bfloat16(a), hb = __float2bfloat16(b);
    float ra = a - __bfloat162float(ha);
    float rb = b - __bfloat162float(hb);
    __nv_bfloat16 la = __float2bfloat16(ra), lb = __float2bfloat16(rb);
    lo_out = (uint32_t)__bfloat16_as_ushort(la) | ((uint32_t)__bfloat16_as_ushort(lb) << 16);
    return (uint32_t)__bfloat16_as_ushort(ha) | ((uint32_t)__bfloat16_as_ushort(hb) << 16);
}

#define RS 80   // smem row stride in bytes (conflict-free for ldmatrix)

// ---------------------------------------------------------------------------
__global__ void k_prep_w(const float* __restrict__ W, int K,
                         __nv_bfloat16* __restrict__ hi, __nv_bfloat16* __restrict__ lo) {
    int i = blockIdx.x * blockDim.x + threadIdx.x;
    if (i < DD * K) {
        int n = i / K, k = i - n * K;
        float w = W[k * DD + n];
        __nv_bfloat16 h = __float2bfloat16(w);
        hi[i] = h;
        lo[i] = __float2bfloat16(w - __bfloat162float(h));
    }
}

__global__ void k_init_deg() {
    int i = blockIdx.x * blockDim.x + threadIdx.x;
    if (i < NN) { g_deg_s[i] = 1; g_deg_r[i] = 1; }
}

__global__ void k_count(const int* __restrict__ senders, const int* __restrict__ receivers) {
    int stride = gridDim.x * blockDim.x;
    for (int e = blockIdx.x * blockDim.x + threadIdx.x; e < NE; e += stride) {
        atomicAdd(&g_deg_s[senders[e]], 1);
        atomicAdd(&g_deg_r[receivers[e]], 1);
    }
}

__global__ void k_scan() {
    __shared__ int ss[1024];
    int t = threadIdx.x;
    const int chunk = (NN + 1023) / 1024;
    int beg = t * chunk;
    int end = beg + chunk; if (end > NN) end = NN;
    int s = 0;
    for (int i = beg; i < end; i++) s += g_deg_r[i] - 1;
    ss[t] = s;
    __syncthreads();
    for (int off = 1; off < 1024; off <<= 1) {
        int v = (t >= off) ? ss[t - off] : 0;
        __syncthreads();
        ss[t] += v;
        __syncthreads();
    }
    int run = (t == 0) ? 0 : ss[t - 1];
    for (int i = beg; i < end; i++) {
        g_rowstart[i] = run;
        g_cursor[i] = run;
        run += g_deg_r[i] - 1;
    }
    if (t == 0) g_rowstart[NN] = ss[1023];
}

__global__ void k_scatter(const int* __restrict__ senders, const int* __restrict__ receivers) {
    int stride = gridDim.x * blockDim.x;
    for (int e = blockIdx.x * blockDim.x + threadIdx.x; e < NE; e += stride) {
        int r = receivers[e];
        int pos = atomicAdd(&g_cursor[r], 1);
        g_esrc[pos] = senders[e];
    }
}

__global__ void k_gather_norm(const int* __restrict__ node_ids, const float* __restrict__ emb) {
    int i = blockIdx.x * blockDim.x + threadIdx.x;
    if (i < NN * (DD / 4)) {
        int node = i >> 5;
        int q = i & 31;
        int src = node_ids[node];
        float4 v = ((const float4*)emb)[src * 32 + q];
        ((float4*)g_x)[i] = v;
        float sc = rsqrtf((float)g_deg_s[node]);
        v.x *= sc; v.y *= sc; v.z *= sc; v.w *= sc;
        ((float4*)g_xnorm)[i] = v;
    }
}

__device__ __forceinline__ float4 f4add(float4 a, float4 b) {
    return make_float4(a.x + b.x, a.y + b.y, a.z + b.z, a.w + b.w);
}

__global__ void k_aggregate() {
    int gw = (blockIdx.x * blockDim.x + threadIdx.x) >> 5;
    if (gw >= NN) return;
    int lane = threadIdx.x & 31;
    const float4* __restrict__ xn = (const float4*)g_xnorm;
    float4 acc = xn[gw * 32 + lane];
    int s = g_rowstart[gw], e = g_rowstart[gw + 1];
    int j = s;
    for (; j + 8 <= e; j += 8) {
        int s0 = g_esrc[j], s1 = g_esrc[j + 1], s2 = g_esrc[j + 2], s3 = g_esrc[j + 3];
        int s4 = g_esrc[j + 4], s5 = g_esrc[j + 5], s6 = g_esrc[j + 6], s7 = g_esrc[j + 7];
        float4 a0 = xn[s0 * 32 + lane];
        float4 a1 = xn[s1 * 32 + lane];
        float4 a2 = xn[s2 * 32 + lane];
        float4 a3 = xn[s3 * 32 + lane];
        float4 a4 = xn[s4 * 32 + lane];
        float4 a5 = xn[s5 * 32 + lane];
        float4 a6 = xn[s6 * 32 + lane];
        float4 a7 = xn[s7 * 32 + lane];
        acc = f4add(acc, f4add(f4add(f4add(a0, a1), f4add(a2, a3)),
                               f4add(f4add(a4, a5), f4add(a6, a7))));
    }
    for (; j < e; j++) acc = f4add(acc, xn[g_esrc[j] * 32 + lane]);
    float cnt = (float)(e - s + 1);
    float sc = rsqrtf(cnt) / cnt;
    acc.x *= sc; acc.y *= sc; acc.z *= sc; acc.w *= sc;
    ((float4*)g_agg)[gw * 32 + lane] = acc;
}

// ---- HMMA layer GEMM: C[128-tile] = act([X|AGG] @ Wt^T + b), K=256 ----
template <bool RELU, bool WRITE_XN>
__global__ void __launch_bounds__(256) k_mgemm_layer(
    const float* __restrict__ X, const float* __restrict__ AGG,
    const __nv_bfloat16* __restrict__ Bhi, const __nv_bfloat16* __restrict__ Blo,
    const float* __restrict__ bias, float* __restrict__ C, float* __restrict__ XN,
    const int* __restrict__ deg, int M)
{
    __shared__ __align__(16) uint8_t sA[2][128 * RS];
    __shared__ __align__(16) uint8_t sB[2][128 * RS];
    int tid = threadIdx.x;
    int lane = tid & 31, wid = tid >> 5;
    int wm = wid & 3, wn = wid >> 2;
    int blk = blockIdx.x * 128;

    float acc[2][8][4];
#pragma unroll
    for (int mt = 0; mt < 2; mt++)
#pragma unroll
        for (int nt = 0; nt < 8; nt++)
#pragma unroll
            for (int i = 0; i < 4; i++) acc[mt][nt][i] = 0.f;

    int srow = tid >> 1, half = tid & 1;
    int grow_s = blk + srow;
    int crow_s = grow_s < M ? grow_s : M - 1;

    uint32_t aHi = smem_u32(sA[0]), aLo = smem_u32(sA[1]);
    uint32_t bHi = smem_u32(sB[0]), bLo = smem_u32(sB[1]);

    // ldmatrix lane-address components
    int a_row = lane & 15, a_k = (lane >> 4) * 16;          // bytes
    int b_row = lane & 7,  b_k = ((lane >> 3) & 1) * 16;    // bytes

    for (int c = 0; c < 8; c++) {
        int kb = c * 32;
        // stage A (fp32 -> bf16 hi/lo, 16 elems per thread)
        {
            const float* src = (c < 4) ? X : AGG;
            const float4* sp = (const float4*)(src + crow_s * DD + (kb & 127)) + half * 4;
            float4 v0 = sp[0], v1 = sp[1], v2 = sp[2], v3 = sp[3];
            uint4 H0, L0, H1, L1;
            H0.x = pack_hilo(v0.x, v0.y, L0.x);
            H0.y = pack_hilo(v0.z, v0.w, L0.y);
            H0.z = pack_hilo(v1.x, v1.y, L0.z);
            H0.w = pack_hilo(v1.z, v1.w, L0.w);
            H1.x = pack_hilo(v2.x, v2.y, L1.x);
            H1.y = pack_hilo(v2.z, v2.w, L1.y);
            H1.z = pack_hilo(v3.x, v3.y, L1.z);
            H1.w = pack_hilo(v3.z, v3.w, L1.w);
            int off = srow * RS + half * 32;
            *(uint4*)(sA[0] + off) = H0;
            *(uint4*)(sA[0] + off + 16) = H1;
            *(uint4*)(sA[1] + off) = L0;
            *(uint4*)(sA[1] + off + 16) = L1;
            // stage B (already bf16 in global)
            const uint4* wh = (const uint4*)(Bhi + srow * 256 + kb + half * 16);
            const uint4* wl = (const uint4*)(Blo + srow * 256 + kb + half * 16);
            *(uint4*)(sB[0] + off) = wh[0];
            *(uint4*)(sB[0] + off + 16) = wh[1];
            *(uint4*)(sB[1] + off) = wl[0];
            *(uint4*)(sB[1] + off + 16) = wl[1];
        }
        __syncthreads();
#pragma unroll
        for (int ks = 0; ks < 2; ks++) {
            uint32_t ah[2][4], al[2][4], bh[8][2], bl[8][2];
#pragma unroll
            for (int mt = 0; mt < 2; mt++) {
                uint32_t ao = (uint32_t)((wm * 32 + mt * 16 + a_row) * RS + ks * 32 + a_k);
                LDSM_X4(ah[mt], aHi + ao);
                LDSM_X4(al[mt], aLo + ao);
            }
#pragma unroll
            for (int nt = 0; nt < 8; nt++) {
                uint32_t bo = (uint32_t)((wn * 64 + nt * 8 + b_row) * RS + ks * 32 + b_k);
                LDSM_X2(bh[nt], bHi + bo);
                LDSM_X2(bl[nt], bLo + bo);
            }
#pragma unroll
            for (int mt = 0; mt < 2; mt++)
#pragma unroll
                for (int nt = 0; nt < 8; nt++) {
                    hmma(acc[mt][nt], ah[mt], bh[nt]);
                    hmma(acc[mt][nt], ah[mt], bl[nt]);
                    hmma(acc[mt][nt], al[mt], bh[nt]);
                }
        }
        __syncthreads();
    }

    // epilogue
#pragma unroll
    for (int mt = 0; mt < 2; mt++) {
        int r0 = blk + wm * 32 + mt * 16 + (lane >> 2);
        int r1 = r0 + 8;
        float s0 = 1.f, s1 = 1.f;
        if (WRITE_XN) {
            s0 = rsqrtf((float)deg[r0 < M ? r0 : M - 1]);
            s1 = rsqrtf((float)deg[r1 < M ? r1 : M - 1]);
        }
#pragma unroll
        for (int nt = 0; nt < 8; nt++) {
            int cc = wn * 64 + nt * 8 + (lane & 3) * 2;
            float2 bv = *(const float2*)(bias + cc);
            float v0 = acc[mt][nt][0] + bv.x;
            float v1 = acc[mt][nt][1] + bv.y;
            float v2 = acc[mt][nt][2] + bv.x;
            float v3 = acc[mt][nt][3] + bv.y;
            if (RELU) {
                v0 = fmaxf(v0, 0.f); v1 = fmaxf(v1, 0.f);
                v2 = fmaxf(v2, 0.f); v3 = fmaxf(v3, 0.f);
            }
            if (r0 < M) {
                *(float2*)(C + r0 * DD + cc) = make_float2(v0, v1);
                if (WRITE_XN) *(float2*)(XN + r0 * DD + cc) = make_float2(v0 * s0, v1 * s0);
            }
            if (r1 < M) {
                *(float2*)(C + r1 * DD + cc) = make_float2(v2, v3);
                if (WRITE_XN) *(float2*)(XN + r1 * DD + cc) = make_float2(v2 * s1, v3 * s1);
            }
        }
    }
}

// ---- HMMA link predictor, K=128, fused relu(z@Wa+ba)@Wb+bb ----
__global__ void __launch_bounds__(256) k_mlinkpred(
    const float* __restrict__ H, const int* __restrict__ pairs,
    const __nv_bfloat16* __restrict__ Bhi, const __nv_bfloat16* __restrict__ Blo,
    const float* __restrict__ ba, const float* __restrict__ Wb,
    const float* __restrict__ bb, float* __restrict__ out)
{
    __shared__ __align__(16) uint8_t sA[2][128 * RS];
    __shared__ __align__(16) uint8_t sB[2][128 * RS];
    __shared__ float sacc[128];
    int tid = threadIdx.x;
    int lane = tid & 31, wid = tid >> 5;
    int wm = wid & 3, wn = wid >> 2;
    int blk = blockIdx.x * 128;

    if (tid < 128) sacc[tid] = 0.f;

    float acc[2][8][4];
#pragma unroll
    for (int mt = 0; mt < 2; mt++)
#pragma unroll
        for (int nt = 0; nt < 8; nt++)
#pragma unroll
            for (int i = 0; i < 4; i++) acc[mt][nt][i] = 0.f;

    int srow = tid >> 1, half = tid & 1;
    int grow_s = blk + srow;
    int crow_s = grow_s < NP ? grow_s : NP - 1;
    int ia = pairs[2 * crow_s];
    int ib = pairs[2 * crow_s + 1];

    uint32_t aHi = smem_u32(sA[0]), aLo = smem_u32(sA[1]);
    uint32_t bHi = smem_u32(sB[0]), bLo = smem_u32(sB[1]);

    int a_row = lane & 15, a_k = (lane >> 4) * 16;
    int b_row = lane & 7,  b_k = ((lane >> 3) & 1) * 16;

    for (int c = 0; c < 4; c++) {
        int kb = c * 32;
        {
            const float4* pa = (const float4*)(H + ia * DD + kb) + half * 4;
            const float4* pb = (const float4*)(H + ib * DD + kb) + half * 4;
            float4 v[4];
#pragma unroll
            for (int i = 0; i < 4; i++) {
                float4 x = pa[i], y = pb[i];
                v[i] = make_float4(x.x * y.x, x.y * y.y, x.z * y.z, x.w * y.w);
            }
            uint4 H0, L0, H1, L1;
            H0.x = pack_hilo(v[0].x, v[0].y, L0.x);
            H0.y = pack_hilo(v[0].z, v[0].w, L0.y);
            H0.z = pack_hilo(v[1].x, v[1].y, L0.z);
            H0.w = pack_hilo(v[1].z, v[1].w, L0.w);
            H1.x = pack_hilo(v[2].x, v[2].y, L1.x);
            H1.y = pack_hilo(v[2].z, v[2].w, L1.y);
            H1.z = pack_hilo(v[3].x, v[3].y, L1.z);
            H1.w = pack_hilo(v[3].z, v[3].w, L1.w);
            int off = srow * RS + half * 32;
            *(uint4*)(sA[0] + off) = H0;
            *(uint4*)(sA[0] + off + 16) = H1;
            *(uint4*)(sA[1] + off) = L0;
            *(uint4*)(sA[1] + off + 16) = L1;
            const uint4* wh = (const uint4*)(Bhi + srow * 128 + kb + half * 16);
            const uint4* wl = (const uint4*)(Blo + srow * 128 + kb + half * 16);
            *(uint4*)(sB[0] + off) = wh[0];
            *(uint4*)(sB[0] + off + 16) = wh[1];
            *(uint4*)(sB[1] + off) = wl[0];
            *(uint4*)(sB[1] + off + 16) = wl[1];
        }
        __syncthreads();
#pragma unroll
        for (int ks = 0; ks < 2; ks++) {
            uint32_t ah[2][4], al[2][4], bh[8][2], bl[8][2];
#pragma unroll
            for (int mt = 0; mt < 2; mt++) {
                uint32_t ao = (uint32_t)((wm * 32 + mt * 16 + a_row) * RS + ks * 32 + a_k);
                LDSM_X4(ah[mt], aHi + ao);
                LDSM_X4(al[mt], aLo + ao);
            }
#pragma unroll
            for (int nt = 0; nt < 8; nt++) {
                uint32_t bo = (uint32_t)((wn * 64 + nt * 8 + b_row) * RS + ks * 32 + b_k);
                LDSM_X2(bh[nt], bHi + bo);
                LDSM_X2(bl[nt], bLo + bo);
            }
#pragma unroll
            for (int mt = 0; mt < 2; mt++)
#pragma unroll
                for (int nt = 0; nt < 8; nt++) {
                    hmma(acc[mt][nt], ah[mt], bh[nt]);
                    hmma(acc[mt][nt], ah[mt], bl[nt]);
                    hmma(acc[mt][nt], al[mt], bh[nt]);
                }
        }
        __syncthreads();
    }

    // epilogue: per-row sum of relu(acc + ba[c]) * Wb[c]
#pragma unroll
    for (int mt = 0; mt < 2; mt++) {
        int lr0 = wm * 32 + mt * 16 + (lane >> 2);
        float p0 = 0.f, p1 = 0.f;
#pragma unroll
        for (int nt = 0; nt < 8; nt++) {
            int cc = wn * 64 + nt * 8 + (lane & 3) * 2;
            float2 bav = *(const float2*)(ba + cc);
            float2 wbv = *(const float2*)(Wb + cc);
            p0 += fmaxf(acc[mt][nt][0] + bav.x, 0.f) * wbv.x
                + fmaxf(acc[mt][nt][1] + bav.y, 0.f) * wbv.y;
            p1 += fmaxf(acc[mt][nt][2] + bav.x, 0.f) * wbv.x
                + fmaxf(acc[mt][nt][3] + bav.y, 0.f) * wbv.y;
        }
        // reduce over the 4 lanes sharing each row
        p0 += __shfl_xor_sync(0xffffffffu, p0, 1);
        p0 += __shfl_xor_sync(0xffffffffu, p0, 2);
        p1 += __shfl_xor_sync(0xffffffffu, p1, 1);
        p1 += __shfl_xor_sync(0xffffffffu, p1, 2);
        if ((lane & 3) == 0) {
            atomicAdd(&sacc[lr0], p0);
            atomicAdd(&sacc[lr0 + 8], p1);
        }
    }
    __syncthreads();
    if (tid < 128) {
        int row = blk + tid;
        if (row < NP) out[row] = sacc[tid] + bb[0];
    }
}

// ---------------------------------------------------------------------------
extern "C" void kernel_launch(void* const* d_in, const int* in_sizes, int n_in,
                              void* d_out, int out_size) {
    const int*   node_ids  = (const int*)d_in[0];
    const int*   senders   = (const int*)d_in[1];
    const int*   receivers = (const int*)d_in[2];
    const int*   pairs     = (const int*)d_in[3];
    const float* emb       = (const float*)d_in[4];
    const float* W1        = (const float*)d_in[5];
    const float* b1        = (const float*)d_in[6];
    const float* W2        = (const float*)d_in[7];
    const float* b2        = (const float*)d_in[8];
    const float* Wa        = (const float*)d_in[9];
    const float* ba        = (const float*)d_in[10];
    const float* Wb        = (const float*)d_in[11];
    const float* bb        = (const float*)d_in[12];
    float* out = (float*)d_out;

    float *x, *h, *ag, *xn;
    int* degs;
    __nv_bfloat16 *w1h, *w1l, *w2h, *w2l, *wah, *wal;
    cudaGetSymbolAddress((void**)&x,  g_x);
    cudaGetSymbolAddress((void**)&h,  g_h);
    cudaGetSymbolAddress((void**)&ag, g_agg);
    cudaGetSymbolAddress((void**)&xn, g_xnorm);
    cudaGetSymbolAddress((void**)&degs, g_deg_s);
    cudaGetSymbolAddress((void**)&w1h, g_w1t_hi);
    cudaGetSymbolAddress((void**)&w1l, g_w1t_lo);
    cudaGetSymbolAddress((void**)&w2h, g_w2t_hi);
    cudaGetSymbolAddress((void**)&w2l, g_w2t_lo);
    cudaGetSymbolAddress((void**)&wah, g_wat_hi);
    cudaGetSymbolAddress((void**)&wal, g_wat_lo);

    const int elem4 = NN * (DD / 4);
    const int vb = (elem4 + 255) / 256;

    k_prep_w<<<(DD * 256 + 255) / 256, 256>>>(W1, 256, w1h, w1l);
    k_prep_w<<<(DD * 256 + 255) / 256, 256>>>(W2, 256, w2h, w2l);
    k_prep_w<<<(DD * DD + 255) / 256, 256>>>(Wa, 128, wah, wal);

    k_init_deg<<<(NN + 255) / 256, 256>>>();
    k_count<<<2048, 256>>>(senders, receivers);
    k_scan<<<1, 1024>>>();
    k_scatter<<<2048, 256>>>(senders, receivers);
    k_gather_norm<<<vb, 256>>>(node_ids, emb);

    // layer 1: x -> h (relu); epilogue also writes xnorm for layer-2 aggregate
    k_aggregate<<<vb, 256>>>();
    k_mgemm_layer<true, true><<<(NN + 127) / 128, 256>>>(
        x, ag, w1h, w1l, b1, h, xn, degs, NN);

    // layer 2: h -> x (no relu)
    k_aggregate<<<vb, 256>>>();
    k_mgemm_layer<false, false><<<(NN + 127) / 128, 256>>>(
        h, ag, w2h, w2l, b2, x, nullptr, degs, NN);

    // link predictor
    k_mlinkpred<<<(NP + 127) / 128, 256>>>(
        x, pairs, wah, wal, ba, Wb, bb, out);
}

// round 5
// speedup vs baseline: 1.4495x; 1.0196x over previous
#include <cuda_runtime.h>
#include <cuda_bf16.h>
#include <cstdint>

#define NN 100000
#define NE 1600000
#define DD 128
#define NP 500000

// ---- scratch (device globals) ----
__device__ __align__(16) float g_x[NN * DD];
__device__ __align__(16) float g_h[NN * DD];
__device__ __align__(16) float g_xnorm[NN * DD];
__device__ __align__(16) float g_agg[NN * DD];
__device__ int g_deg_s[NN];
__device__ int g_deg_r[NN];
__device__ int g_rowstart[NN + 1];
__device__ int g_cursor[NN];
__device__ int g_esrc[NE];
// transposed, hi/lo-split weights: Wt[n][k] = W[k][n]
__device__ __align__(16) __nv_bfloat16 g_w1t_hi[DD * 256];
__device__ __align__(16) __nv_bfloat16 g_w1t_lo[DD * 256];
__device__ __align__(16) __nv_bfloat16 g_w2t_hi[DD * 256];
__device__ __align__(16) __nv_bfloat16 g_w2t_lo[DD * 256];
__device__ __align__(16) __nv_bfloat16 g_wat_hi[DD * DD];
__device__ __align__(16) __nv_bfloat16 g_wat_lo[DD * DD];

// ---- helpers ----
__device__ __forceinline__ uint32_t smem_u32(const void* p) {
    uint32_t a;
    asm("{.reg .u64 t; cvta.to.shared.u64 t, %1; cvt.u32.u64 %0, t;}" : "=r"(a) : "l"(p));
    return a;
}
#define LDSM_X4(r, a) \
    asm volatile("ldmatrix.sync.aligned.m8n8.x4.shared.b16 {%0,%1,%2,%3}, [%4];" \
        : "=r"((r)[0]), "=r"((r)[1]), "=r"((r)[2]), "=r"((r)[3]) : "r"(a))
__device__ __forceinline__ void hmma(float* d, const uint32_t* a, const uint32_t* b) {
    asm volatile(
        "mma.sync.aligned.m16n8k16.row.col.f32.bf16.bf16.f32 "
        "{%0,%1,%2,%3}, {%4,%5,%6,%7}, {%8,%9}, {%0,%1,%2,%3};"
        : "+f"(d[0]), "+f"(d[1]), "+f"(d[2]), "+f"(d[3])
        : "r"(a[0]), "r"(a[1]), "r"(a[2]), "r"(a[3]), "r"(b[0]), "r"(b[1]));
}
__device__ __forceinline__ uint32_t pack_hilo(float a, float b, uint32_t& lo_out) {
    __nv_bfloat16 ha = __float2bfloat16(a), hb = __float2bfloat16(b);
    float ra = a - __bfloat162float(ha);
    float rb = b - __bfloat162float(hb);
    __nv_bfloat16 la = __float2bfloat16(ra), lb = __float2bfloat16(rb);
    lo_out = (uint32_t)__bfloat16_as_ushort(la) | ((uint32_t)__bfloat16_as_ushort(lb) << 16);
    return (uint32_t)__bfloat16_as_ushort(ha) | ((uint32_t)__bfloat16_as_ushort(hb) << 16);
}

#define RS 80   // smem row stride in bytes (conflict-free for ldmatrix)

// ---------------------------------------------------------------------------
// fused prep: split/transpose W1,W2,Wa + init degree arrays (one launch)
__global__ void k_prep_all(const float* __restrict__ W1, const float* __restrict__ W2,
                           const float* __restrict__ Wa) {
    int i = blockIdx.x * blockDim.x + threadIdx.x;
    if (i < DD * 256) {
        int n = i / 256, k = i - n * 256;
        float w = W1[k * DD + n];
        __nv_bfloat16 h = __float2bfloat16(w);
        g_w1t_hi[i] = h;
        g_w1t_lo[i] = __float2bfloat16(w - __bfloat162float(h));
        float w2 = W2[k * DD + n];
        __nv_bfloat16 h2 = __float2bfloat16(w2);
        g_w2t_hi[i] = h2;
        g_w2t_lo[i] = __float2bfloat16(w2 - __bfloat162float(h2));
    }
    if (i < DD * DD) {
        int n = i / DD, k = i - n * DD;
        float w = Wa[k * DD + n];
        __nv_bfloat16 h = __float2bfloat16(w);
        g_wat_hi[i] = h;
        g_wat_lo[i] = __float2bfloat16(w - __bfloat162float(h));
    }
    if (i < NN) { g_deg_s[i] = 1; g_deg_r[i] = 1; }
}

__global__ void k_count(const int* __restrict__ senders, const int* __restrict__ receivers) {
    int stride = gridDim.x * blockDim.x;
    for (int e = blockIdx.x * blockDim.x + threadIdx.x; e < NE; e += stride) {
        atomicAdd(&g_deg_s[senders[e]], 1);
        atomicAdd(&g_deg_r[receivers[e]], 1);
    }
}

__global__ void k_scan() {
    __shared__ int ss[1024];
    int t = threadIdx.x;
    const int chunk = (NN + 1023) / 1024;
    int beg = t * chunk;
    int end = beg + chunk; if (end > NN) end = NN;
    int s = 0;
    for (int i = beg; i < end; i++) s += g_deg_r[i] - 1;
    ss[t] = s;
    __syncthreads();
    for (int off = 1; off < 1024; off <<= 1) {
        int v = (t >= off) ? ss[t - off] : 0;
        __syncthreads();
        ss[t] += v;
        __syncthreads();
    }
    int run = (t == 0) ? 0 : ss[t - 1];
    for (int i = beg; i < end; i++) {
        g_rowstart[i] = run;
        g_cursor[i] = run;
        run += g_deg_r[i] - 1;
    }
    if (t == 0) g_rowstart[NN] = ss[1023];
}

__global__ void k_scatter(const int* __restrict__ senders, const int* __restrict__ receivers) {
    int stride = gridDim.x * blockDim.x;
    for (int e = blockIdx.x * blockDim.x + threadIdx.x; e < NE; e += stride) {
        int r = receivers[e];
        int pos = atomicAdd(&g_cursor[r], 1);
        g_esrc[pos] = senders[e];
    }
}

__global__ void k_gather_norm(const int* __restrict__ node_ids, const float* __restrict__ emb) {
    int i = blockIdx.x * blockDim.x + threadIdx.x;
    if (i < NN * (DD / 4)) {
        int node = i >> 5;
        int q = i & 31;
        int src = node_ids[node];
        float4 v = ((const float4*)emb)[src * 32 + q];
        ((float4*)g_x)[i] = v;
        float sc = rsqrtf((float)g_deg_s[node]);
        v.x *= sc; v.y *= sc; v.z *= sc; v.w *= sc;
        ((float4*)g_xnorm)[i] = v;
    }
}

__device__ __forceinline__ float4 f4add(float4 a, float4 b) {
    return make_float4(a.x + b.x, a.y + b.y, a.z + b.z, a.w + b.w);
}

__global__ void k_aggregate() {
    int gw = (blockIdx.x * blockDim.x + threadIdx.x) >> 5;
    if (gw >= NN) return;
    int lane = threadIdx.x & 31;
    const float4* __restrict__ xn = (const float4*)g_xnorm;
    float4 acc = xn[gw * 32 + lane];
    int s = g_rowstart[gw], e = g_rowstart[gw + 1];
    int j = s;
    for (; j + 8 <= e; j += 8) {
        int s0 = g_esrc[j], s1 = g_esrc[j + 1], s2 = g_esrc[j + 2], s3 = g_esrc[j + 3];
        int s4 = g_esrc[j + 4], s5 = g_esrc[j + 5], s6 = g_esrc[j + 6], s7 = g_esrc[j + 7];
        float4 a0 = xn[s0 * 32 + lane];
        float4 a1 = xn[s1 * 32 + lane];
        float4 a2 = xn[s2 * 32 + lane];
        float4 a3 = xn[s3 * 32 + lane];
        float4 a4 = xn[s4 * 32 + lane];
        float4 a5 = xn[s5 * 32 + lane];
        float4 a6 = xn[s6 * 32 + lane];
        float4 a7 = xn[s7 * 32 + lane];
        acc = f4add(acc, f4add(f4add(f4add(a0, a1), f4add(a2, a3)),
                               f4add(f4add(a4, a5), f4add(a6, a7))));
    }
    for (; j < e; j++) acc = f4add(acc, xn[g_esrc[j] * 32 + lane]);
    float cnt = (float)(e - s + 1);
    float sc = rsqrtf(cnt) / cnt;
    acc.x *= sc; acc.y *= sc; acc.z *= sc; acc.w *= sc;
    ((float4*)g_agg)[gw * 32 + lane] = acc;
}

// shared-memory store of one staged chunk (A from fp32 regs, B from bf16 regs)
__device__ __forceinline__ void stage_store(
    uint8_t (*sA)[128 * RS], uint8_t (*sB)[128 * RS], int off,
    const float4* pv, const uint4* pwh, const uint4* pwl)
{
    uint4 H0, L0, H1, L1;
    H0.x = pack_hilo(pv[0].x, pv[0].y, L0.x);
    H0.y = pack_hilo(pv[0].z, pv[0].w, L0.y);
    H0.z = pack_hilo(pv[1].x, pv[1].y, L0.z);
    H0.w = pack_hilo(pv[1].z, pv[1].w, L0.w);
    H1.x = pack_hilo(pv[2].x, pv[2].y, L1.x);
    H1.y = pack_hilo(pv[2].z, pv[2].w, L1.y);
    H1.z = pack_hilo(pv[3].x, pv[3].y, L1.z);
    H1.w = pack_hilo(pv[3].z, pv[3].w, L1.w);
    *(uint4*)(sA[0] + off) = H0;
    *(uint4*)(sA[0] + off + 16) = H1;
    *(uint4*)(sA[1] + off) = L0;
    *(uint4*)(sA[1] + off + 16) = L1;
    *(uint4*)(sB[0] + off) = pwh[0];
    *(uint4*)(sB[0] + off + 16) = pwh[1];
    *(uint4*)(sB[1] + off) = pwl[0];
    *(uint4*)(sB[1] + off + 16) = pwl[1];
}

// MMA compute for one staged chunk (2 k16-steps, 3-term split)
__device__ __forceinline__ void chunk_compute(
    float (*acc)[8][4], uint32_t aHi, uint32_t aLo, uint32_t bHi, uint32_t bLo,
    int wm, int wn, int lane)
{
    int a_row = lane & 15, a_k = (lane >> 4) * 16;
    int b_addr_row = (lane & 7) + 8 * ((lane >> 4) & 1);
    int b_k = ((lane >> 3) & 1) * 16;
#pragma unroll
    for (int ks = 0; ks < 2; ks++) {
        uint32_t ah[2][4], al[2][4], bh[8][2], bl[8][2];
#pragma unroll
        for (int mt = 0; mt < 2; mt++) {
            uint32_t ao = (uint32_t)((wm * 32 + mt * 16 + a_row) * RS + ks * 32 + a_k);
            LDSM_X4(ah[mt], aHi + ao);
            LDSM_X4(al[mt], aLo + ao);
        }
#pragma unroll
        for (int np = 0; np < 4; np++) {
            uint32_t bo = (uint32_t)((wn * 64 + np * 16 + b_addr_row) * RS + ks * 32 + b_k);
            uint32_t r4[4];
            LDSM_X4(r4, bHi + bo);
            bh[2 * np][0] = r4[0]; bh[2 * np][1] = r4[1];
            bh[2 * np + 1][0] = r4[2]; bh[2 * np + 1][1] = r4[3];
            LDSM_X4(r4, bLo + bo);
            bl[2 * np][0] = r4[0]; bl[2 * np][1] = r4[1];
            bl[2 * np + 1][0] = r4[2]; bl[2 * np + 1][1] = r4[3];
        }
#pragma unroll
        for (int mt = 0; mt < 2; mt++)
#pragma unroll
            for (int nt = 0; nt < 8; nt++) {
                hmma(acc[mt][nt], ah[mt], bh[nt]);
                hmma(acc[mt][nt], ah[mt], bl[nt]);
                hmma(acc[mt][nt], al[mt], bh[nt]);
            }
    }
}

// ---- HMMA layer GEMM: C[128-tile] = act([X|AGG] @ Wt^T + b), K=256 ----
template <bool RELU, bool WRITE_XN>
__global__ void __launch_bounds__(256) k_mgemm_layer(
    const float* __restrict__ X, const float* __restrict__ AGG,
    const __nv_bfloat16* __restrict__ Bhi, const __nv_bfloat16* __restrict__ Blo,
    const float* __restrict__ bias, float* __restrict__ C, float* __restrict__ XN,
    const int* __restrict__ deg, int M)
{
    __shared__ __align__(16) uint8_t sA[2][128 * RS];
    __shared__ __align__(16) uint8_t sB[2][128 * RS];
    int tid = threadIdx.x;
    int lane = tid & 31, wid = tid >> 5;
    int wm = wid & 3, wn = wid >> 2;
    int blk = blockIdx.x * 128;

    float acc[2][8][4];
#pragma unroll
    for (int mt = 0; mt < 2; mt++)
#pragma unroll
        for (int nt = 0; nt < 8; nt++)
#pragma unroll
            for (int i = 0; i < 4; i++) acc[mt][nt][i] = 0.f;

    int srow = tid >> 1, half = tid & 1;
    int grow_s = blk + srow;
    int crow_s = grow_s < M ? grow_s : M - 1;
    int off = srow * RS + half * 32;

    uint32_t aHi = smem_u32(sA[0]), aLo = smem_u32(sA[1]);
    uint32_t bHi = smem_u32(sB[0]), bLo = smem_u32(sB[1]);

    float4 pv[4];
    uint4 pwh[2], pwl[2];
    // prefetch chunk 0
    {
        const float4* sp = (const float4*)(X + crow_s * DD) + half * 4;
        pv[0] = sp[0]; pv[1] = sp[1]; pv[2] = sp[2]; pv[3] = sp[3];
        const uint4* wh = (const uint4*)(Bhi + srow * 256 + half * 16);
        const uint4* wl = (const uint4*)(Blo + srow * 256 + half * 16);
        pwh[0] = wh[0]; pwh[1] = wh[1]; pwl[0] = wl[0]; pwl[1] = wl[1];
    }

    for (int c = 0; c < 8; c++) {
        stage_store(sA, sB, off, pv, pwh, pwl);
        __syncthreads();
        if (c < 7) {
            int kb = (c + 1) * 32;
            const float* src = (c + 1 < 4) ? X : AGG;
            const float4* sp = (const float4*)(src + crow_s * DD + (kb & 127)) + half * 4;
            pv[0] = sp[0]; pv[1] = sp[1]; pv[2] = sp[2]; pv[3] = sp[3];
            const uint4* wh = (const uint4*)(Bhi + srow * 256 + kb + half * 16);
            const uint4* wl = (const uint4*)(Blo + srow * 256 + kb + half * 16);
            pwh[0] = wh[0]; pwh[1] = wh[1]; pwl[0] = wl[0]; pwl[1] = wl[1];
        }
        chunk_compute(acc, aHi, aLo, bHi, bLo, wm, wn, lane);
        __syncthreads();
    }

    // epilogue
#pragma unroll
    for (int mt = 0; mt < 2; mt++) {
        int r0 = blk + wm * 32 + mt * 16 + (lane >> 2);
        int r1 = r0 + 8;
        float s0 = 1.f, s1 = 1.f;
        if (WRITE_XN) {
            s0 = rsqrtf((float)deg[r0 < M ? r0 : M - 1]);
            s1 = rsqrtf((float)deg[r1 < M ? r1 : M - 1]);
        }
#pragma unroll
        for (int nt = 0; nt < 8; nt++) {
            int cc = wn * 64 + nt * 8 + (lane & 3) * 2;
            float2 bv = *(const float2*)(bias + cc);
            float v0 = acc[mt][nt][0] + bv.x;
            float v1 = acc[mt][nt][1] + bv.y;
            float v2 = acc[mt][nt][2] + bv.x;
            float v3 = acc[mt][nt][3] + bv.y;
            if (RELU) {
                v0 = fmaxf(v0, 0.f); v1 = fmaxf(v1, 0.f);
                v2 = fmaxf(v2, 0.f); v3 = fmaxf(v3, 0.f);
            }
            if (r0 < M) {
                *(float2*)(C + r0 * DD + cc) = make_float2(v0, v1);
                if (WRITE_XN) *(float2*)(XN + r0 * DD + cc) = make_float2(v0 * s0, v1 * s0);
            }
            if (r1 < M) {
                *(float2*)(C + r1 * DD + cc) = make_float2(v2, v3);
                if (WRITE_XN) *(float2*)(XN + r1 * DD + cc) = make_float2(v2 * s1, v3 * s1);
            }
        }
    }
}

// ---- HMMA link predictor, K=128, fused relu(z@Wa+ba)@Wb+bb ----
__global__ void __launch_bounds__(256) k_mlinkpred(
    const float* __restrict__ H, const int* __restrict__ pairs,
    const __nv_bfloat16* __restrict__ Bhi, const __nv_bfloat16* __restrict__ Blo,
    const float* __restrict__ ba, const float* __restrict__ Wb,
    const float* __restrict__ bb, float* __restrict__ out)
{
    __shared__ __align__(16) uint8_t sA[2][128 * RS];
    __shared__ __align__(16) uint8_t sB[2][128 * RS];
    __shared__ float sacc[128];
    int tid = threadIdx.x;
    int lane = tid & 31, wid = tid >> 5;
    int wm = wid & 3, wn = wid >> 2;
    int blk = blockIdx.x * 128;

    if (tid < 128) sacc[tid] = 0.f;

    float acc[2][8][4];
#pragma unroll
    for (int mt = 0; mt < 2; mt++)
#pragma unroll
        for (int nt = 0; nt < 8; nt++)
#pragma unroll
            for (int i = 0; i < 4; i++) acc[mt][nt][i] = 0.f;

    int srow = tid >> 1, half = tid & 1;
    int grow_s = blk + srow;
    int crow_s = grow_s < NP ? grow_s : NP - 1;
    int ia = pairs[2 * crow_s];
    int ib = pairs[2 * crow_s + 1];
    int off = srow * RS + half * 32;

    uint32_t aHi = smem_u32(sA[0]), aLo = smem_u32(sA[1]);
    uint32_t bHi = smem_u32(sB[0]), bLo = smem_u32(sB[1]);

    float4 pv[4];
    uint4 pwh[2], pwl[2];
    auto prefetch = [&](int c) {
        int kb = c * 32;
        const float4* pa = (const float4*)(H + ia * DD + kb) + half * 4;
        const float4* pb = (const float4*)(H + ib * DD + kb) + half * 4;
#pragma unroll
        for (int i = 0; i < 4; i++) {
            float4 x = pa[i], y = pb[i];
            pv[i] = make_float4(x.x * y.x, x.y * y.y, x.z * y.z, x.w * y.w);
        }
        const uint4* wh = (const uint4*)(Bhi + srow * 128 + kb + half * 16);
        const uint4* wl = (const uint4*)(Blo + srow * 128 + kb + half * 16);
        pwh[0] = wh[0]; pwh[1] = wh[1]; pwl[0] = wl[0]; pwl[1] = wl[1];
    };

    prefetch(0);
    for (int c = 0; c < 4; c++) {
        stage_store(sA, sB, off, pv, pwh, pwl);
        __syncthreads();
        if (c < 3) prefetch(c + 1);
        chunk_compute(acc, aHi, aLo, bHi, bLo, wm, wn, lane);
        __syncthreads();
    }

    // epilogue: per-row sum of relu(acc + ba[c]) * Wb[c]
#pragma unroll
    for (int mt = 0; mt < 2; mt++) {
        int lr0 = wm * 32 + mt * 16 + (lane >> 2);
        float p0 = 0.f, p1 = 0.f;
#pragma unroll
        for (int nt = 0; nt < 8; nt++) {
            int cc = wn * 64 + nt * 8 + (lane & 3) * 2;
            float2 bav = *(const float2*)(ba + cc);
            float2 wbv = *(const float2*)(Wb + cc);
            p0 += fmaxf(acc[mt][nt][0] + bav.x, 0.f) * wbv.x
                + fmaxf(acc[mt][nt][1] + bav.y, 0.f) * wbv.y;
            p1 += fmaxf(acc[mt][nt][2] + bav.x, 0.f) * wbv.x
                + fmaxf(acc[mt][nt][3] + bav.y, 0.f) * wbv.y;
        }
        p0 += __shfl_xor_sync(0xffffffffu, p0, 1);
        p0 += __shfl_xor_sync(0xffffffffu, p0, 2);
        p1 += __shfl_xor_sync(0xffffffffu, p1, 1);
        p1 += __shfl_xor_sync(0xffffffffu, p1, 2);
        if ((lane & 3) == 0) {
            atomicAdd(&sacc[lr0], p0);
            atomicAdd(&sacc[lr0 + 8], p1);
        }
    }
    __syncthreads();
    if (tid < 128) {
        int row = blk + tid;
        if (row < NP) out[row] = sacc[tid] + bb[0];
    }
}

// ---------------------------------------------------------------------------
extern "C" void kernel_launch(void* const* d_in, const int* in_sizes, int n_in,
                              void* d_out, int out_size) {
    const int*   node_ids  = (const int*)d_in[0];
    const int*   senders   = (const int*)d_in[1];
    const int*   receivers = (const int*)d_in[2];
    const int*   pairs     = (const int*)d_in[3];
    const float* emb       = (const float*)d_in[4];
    const float* W1        = (const float*)d_in[5];
    const float* b1        = (const float*)d_in[6];
    const float* W2        = (const float*)d_in[7];
    const float* b2        = (const float*)d_in[8];
    const float* Wa        = (const float*)d_in[9];
    const float* ba        = (const float*)d_in[10];
    const float* Wb        = (const float*)d_in[11];
    const float* bb        = (const float*)d_in[12];
    float* out = (float*)d_out;

    float *x, *h, *ag, *xn;
    int* degs;
    __nv_bfloat16 *w1h, *w1l, *w2h, *w2l, *wah, *wal;
    cudaGetSymbolAddress((void**)&x,  g_x);
    cudaGetSymbolAddress((void**)&h,  g_h);
    cudaGetSymbolAddress((void**)&ag, g_agg);
    cudaGetSymbolAddress((void**)&xn, g_xnorm);
    cudaGetSymbolAddress((void**)&degs, g_deg_s);
    cudaGetSymbolAddress((void**)&w1h, g_w1t_hi);
    cudaGetSymbolAddress((void**)&w1l, g_w1t_lo);
    cudaGetSymbolAddress((void**)&w2h, g_w2t_hi);
    cudaGetSymbolAddress((void**)&w2l, g_w2t_lo);
    cudaGetSymbolAddress((void**)&wah, g_wat_hi);
    cudaGetSymbolAddress((void**)&wal, g_wat_lo);

    const int elem4 = NN * (DD / 4);
    const int vb = (elem4 + 255) / 256;

    k_prep_all<<<(NN + 255) / 256, 256>>>(W1, W2, Wa);
    k_count<<<2048, 256>>>(senders, receivers);
    k_scan<<<1, 1024>>>();
    k_scatter<<<2048, 256>>>(senders, receivers);
    k_gather_norm<<<vb, 256>>>(node_ids, emb);

    // layer 1: x -> h (relu); epilogue also writes xnorm for layer-2 aggregate
    k_aggregate<<<vb, 256>>>();
    k_mgemm_layer<true, true><<<(NN + 127) / 128, 256>>>(
        x, ag, w1h, w1l, b1, h, xn, degs, NN);

    // layer 2: h -> x (no relu)
    k_aggregate<<<vb, 256>>>();
    k_mgemm_layer<false, false><<<(NN + 127) / 128, 256>>>(
        h, ag, w2h, w2l, b2, x, nullptr, degs, NN);

    // link predictor
    k_mlinkpred<<<(NP + 127) / 128, 256>>>(
        x, pairs, wah, wal, ba, Wb, bb, out);
}

// round 6
// speedup vs baseline: 1.7470x; 1.2052x over previous
#include <cuda_runtime.h>
#include <cuda_fp16.h>
#include <cstdint>

#define NN 100000
#define NE 1600000
#define DD 128
#define NP 500000
#define NG4 (NN * 32)   // gather work items (float4 granularity)

// ---- scratch (device globals) ----
__device__ __align__(16) float g_x[NN * DD];
__device__ __align__(16) float g_h[NN * DD];
__device__ __align__(16) float g_xnorm[NN * DD];
__device__ __align__(16) float g_agg[NN * DD];
__device__ int g_deg_s[NN];
__device__ int g_deg_r[NN];
__device__ int g_rowstart[NN + 1];
__device__ int g_cursor[NN];
__device__ int g_esrc[NE];
__device__ unsigned g_ticket;
// transposed fp16 weights: Wt[n][k] = W[k][n]
__device__ __align__(16) __half g_w1t[DD * 256];
__device__ __align__(16) __half g_w2t[DD * 256];
__device__ __align__(16) __half g_wat[DD * DD];

// ---- helpers ----
__device__ __forceinline__ uint32_t smem_u32(const void* p) {
    uint32_t a;
    asm("{.reg .u64 t; cvta.to.shared.u64 t, %1; cvt.u32.u64 %0, t;}" : "=r"(a) : "l"(p));
    return a;
}
#define LDSM_X4(r, a) \
    asm volatile("ldmatrix.sync.aligned.m8n8.x4.shared.b16 {%0,%1,%2,%3}, [%4];" \
        : "=r"((r)[0]), "=r"((r)[1]), "=r"((r)[2]), "=r"((r)[3]) : "r"(a))
__device__ __forceinline__ void hmma(float* d, const uint32_t* a, const uint32_t* b) {
    asm volatile(
        "mma.sync.aligned.m16n8k16.row.col.f32.f16.f16.f32 "
        "{%0,%1,%2,%3}, {%4,%5,%6,%7}, {%8,%9}, {%0,%1,%2,%3};"
        : "+f"(d[0]), "+f"(d[1]), "+f"(d[2]), "+f"(d[3])
        : "r"(a[0]), "r"(a[1]), "r"(a[2]), "r"(a[3]), "r"(b[0]), "r"(b[1]));
}
// fp16 hi/lo split pack: returns packed (hi(a),hi(b)), writes packed lo
__device__ __forceinline__ uint32_t pack_h2(float a, float b, uint32_t& lo_out) {
    __half ha = __float2half_rn(a), hb = __float2half_rn(b);
    __half la = __float2half_rn(a - __half2float(ha));
    __half lb = __float2half_rn(b - __half2float(hb));
    lo_out = (uint32_t)__half_as_ushort(la) | ((uint32_t)__half_as_ushort(lb) << 16);
    return (uint32_t)__half_as_ushort(ha) | ((uint32_t)__half_as_ushort(hb) << 16);
}

#define RS 80   // smem row stride in bytes (conflict-free for ldmatrix)

// ---------------------------------------------------------------------------
// 1) prep: transpose+convert weights to fp16, init degree arrays, reset ticket
__global__ void k_prep_all(const float* __restrict__ W1, const float* __restrict__ W2,
                           const float* __restrict__ Wa) {
    int i = blockIdx.x * blockDim.x + threadIdx.x;
    if (i < DD * 256) {
        int n = i >> 8, k = i & 255;
        g_w1t[i] = __float2half_rn(W1[k * DD + n]);
        g_w2t[i] = __float2half_rn(W2[k * DD + n]);
    }
    if (i < DD * DD) {
        int n = i >> 7, k = i & 127;
        g_wat[i] = __float2half_rn(Wa[k * DD + n]);
    }
    if (i < NN) { g_deg_s[i] = 1; g_deg_r[i] = 1; }
    if (i == 0) g_ticket = 0;
}

// 2) count degrees; last block performs the exclusive scan (ticket pattern)
__global__ void k_count_scan(const int* __restrict__ senders, const int* __restrict__ receivers) {
    int stride = gridDim.x * blockDim.x;
    for (int e = blockIdx.x * blockDim.x + threadIdx.x; e < NE; e += stride) {
        atomicAdd(&g_deg_s[senders[e]], 1);
        atomicAdd(&g_deg_r[receivers[e]], 1);
    }
    __threadfence();
    __shared__ unsigned s_last;
    __syncthreads();
    if (threadIdx.x == 0) s_last = atomicAdd(&g_ticket, 1);
    __syncthreads();
    if (s_last != gridDim.x - 1) return;

    // last block: 256-thread exclusive scan of (deg_r - 1)
    __shared__ int ss[256];
    int t = threadIdx.x;
    const int chunk = (NN + 255) / 256;   // 391
    int beg = t * chunk;
    int end = beg + chunk; if (end > NN) end = NN;
    int s = 0;
    for (int i = beg; i < end; i++) s += __ldcg(&g_deg_r[i]) - 1;
    ss[t] = s;
    __syncthreads();
    for (int off = 1; off < 256; off <<= 1) {
        int v = (t >= off) ? ss[t - off] : 0;
        __syncthreads();
        ss[t] += v;
        __syncthreads();
    }
    int run = (t == 0) ? 0 : ss[t - 1];
    for (int i = beg; i < end; i++) {
        g_rowstart[i] = run;
        g_cursor[i] = run;
        run += __ldcg(&g_deg_r[i]) - 1;
    }
    if (t == 255) g_rowstart[NN] = ss[255];
}

// 3) fused: CSR scatter + gather x0/xnorm (independent work, one launch)
__global__ void k_scatter_gather(const int* __restrict__ senders,
                                 const int* __restrict__ receivers,
                                 const int* __restrict__ node_ids,
                                 const float* __restrict__ emb) {
    int i = blockIdx.x * blockDim.x + threadIdx.x;
    if (i < NG4) {
        int node = i >> 5;
        int q = i & 31;
        int src = node_ids[node];
        float4 v = ((const float4*)emb)[src * 32 + q];
        ((float4*)g_x)[i] = v;
        float sc = rsqrtf((float)g_deg_s[node]);
        v.x *= sc; v.y *= sc; v.z *= sc; v.w *= sc;
        ((float4*)g_xnorm)[i] = v;
    } else {
        int e = i - NG4;
        if (e < NE) {
            int r = receivers[e];
            int pos = atomicAdd(&g_cursor[r], 1);
            g_esrc[pos] = senders[e];
        }
    }
}

__device__ __forceinline__ float4 f4add(float4 a, float4 b) {
    return make_float4(a.x + b.x, a.y + b.y, a.z + b.z, a.w + b.w);
}

// 4) aggregate (PROFILED SLOT): warp per node
__global__ void k_aggregate() {
    int gw = (blockIdx.x * blockDim.x + threadIdx.x) >> 5;
    if (gw >= NN) return;
    int lane = threadIdx.x & 31;
    const float4* __restrict__ xn = (const float4*)g_xnorm;
    float4 acc = xn[gw * 32 + lane];
    int s = g_rowstart[gw], e = g_rowstart[gw + 1];
    int j = s;
    for (; j + 8 <= e; j += 8) {
        int s0 = g_esrc[j], s1 = g_esrc[j + 1], s2 = g_esrc[j + 2], s3 = g_esrc[j + 3];
        int s4 = g_esrc[j + 4], s5 = g_esrc[j + 5], s6 = g_esrc[j + 6], s7 = g_esrc[j + 7];
        float4 a0 = xn[s0 * 32 + lane];
        float4 a1 = xn[s1 * 32 + lane];
        float4 a2 = xn[s2 * 32 + lane];
        float4 a3 = xn[s3 * 32 + lane];
        float4 a4 = xn[s4 * 32 + lane];
        float4 a5 = xn[s5 * 32 + lane];
        float4 a6 = xn[s6 * 32 + lane];
        float4 a7 = xn[s7 * 32 + lane];
        acc = f4add(acc, f4add(f4add(f4add(a0, a1), f4add(a2, a3)),
                               f4add(f4add(a4, a5), f4add(a6, a7))));
    }
    for (; j < e; j++) acc = f4add(acc, xn[g_esrc[j] * 32 + lane]);
    float cnt = (float)(e - s + 1);
    float sc = rsqrtf(cnt) / cnt;
    acc.x *= sc; acc.y *= sc; acc.z *= sc; acc.w *= sc;
    ((float4*)g_agg)[gw * 32 + lane] = acc;
}

// MMA compute for one staged chunk (fp16, 2-term split on A)
__device__ __forceinline__ void chunk_compute(
    float (*acc)[8][4], uint32_t aHi, uint32_t aLo, uint32_t aB,
    int wm, int wn, int lane)
{
    int a_row = lane & 15, a_k = (lane >> 4) * 16;
    int b_addr_row = (lane & 7) + 8 * ((lane >> 4) & 1);
    int b_k = ((lane >> 3) & 1) * 16;
#pragma unroll
    for (int ks = 0; ks < 2; ks++) {
        uint32_t ah[2][4], al[2][4], b[8][2];
#pragma unroll
        for (int mt = 0; mt < 2; mt++) {
            uint32_t ao = (uint32_t)((wm * 32 + mt * 16 + a_row) * RS + ks * 32 + a_k);
            LDSM_X4(ah[mt], aHi + ao);
            LDSM_X4(al[mt], aLo + ao);
        }
#pragma unroll
        for (int np = 0; np < 4; np++) {
            uint32_t bo = (uint32_t)((wn * 64 + np * 16 + b_addr_row) * RS + ks * 32 + b_k);
            uint32_t r4[4];
            LDSM_X4(r4, aB + bo);
            b[2 * np][0] = r4[0]; b[2 * np][1] = r4[1];
            b[2 * np + 1][0] = r4[2]; b[2 * np + 1][1] = r4[3];
        }
#pragma unroll
        for (int mt = 0; mt < 2; mt++)
#pragma unroll
            for (int nt = 0; nt < 8; nt++) {
                hmma(acc[mt][nt], ah[mt], b[nt]);
                hmma(acc[mt][nt], al[mt], b[nt]);
            }
    }
}

// stage one chunk: A fp32 -> fp16 hi/lo; B fp16 passthrough
__device__ __forceinline__ void stage_chunk(
    uint8_t* sAh, uint8_t* sAl, uint8_t* sB, int off,
    const float4* sp, const uint4* wp)
{
    float4 v0 = sp[0], v1 = sp[1], v2 = sp[2], v3 = sp[3];
    uint4 H0, L0, H1, L1;
    H0.x = pack_h2(v0.x, v0.y, L0.x);
    H0.y = pack_h2(v0.z, v0.w, L0.y);
    H0.z = pack_h2(v1.x, v1.y, L0.z);
    H0.w = pack_h2(v1.z, v1.w, L0.w);
    H1.x = pack_h2(v2.x, v2.y, L1.x);
    H1.y = pack_h2(v2.z, v2.w, L1.y);
    H1.z = pack_h2(v3.x, v3.y, L1.z);
    H1.w = pack_h2(v3.z, v3.w, L1.w);
    *(uint4*)(sAh + off) = H0;
    *(uint4*)(sAh + off + 16) = H1;
    *(uint4*)(sAl + off) = L0;
    *(uint4*)(sAl + off + 16) = L1;
    *(uint4*)(sB + off) = wp[0];
    *(uint4*)(sB + off + 16) = wp[1];
}

// ---- HMMA layer GEMM: C[128-tile] = act([X|AGG] @ Wt^T + b), K=256 ----
template <bool RELU, bool WRITE_XN>
__global__ void __launch_bounds__(256, 2) k_mgemm_layer(
    const float* __restrict__ X, const float* __restrict__ AGG,
    const __half* __restrict__ Bw,
    const float* __restrict__ bias, float* __restrict__ C, float* __restrict__ XN,
    const int* __restrict__ deg, int M)
{
    __shared__ __align__(16) uint8_t sAh[128 * RS];
    __shared__ __align__(16) uint8_t sAl[128 * RS];
    __shared__ __align__(16) uint8_t sB[128 * RS];
    int tid = threadIdx.x;
    int lane = tid & 31, wid = tid >> 5;
    int wm = wid & 3, wn = wid >> 2;
    int blk = blockIdx.x * 128;

    float acc[2][8][4];
#pragma unroll
    for (int mt = 0; mt < 2; mt++)
#pragma unroll
        for (int nt = 0; nt < 8; nt++)
#pragma unroll
            for (int i = 0; i < 4; i++) acc[mt][nt][i] = 0.f;

    int srow = tid >> 1, half = tid & 1;
    int grow_s = blk + srow;
    int crow_s = grow_s < M ? grow_s : M - 1;
    int off = srow * RS + half * 32;

    uint32_t aHi = smem_u32(sAh), aLo = smem_u32(sAl), aB = smem_u32(sB);

    for (int c = 0; c < 8; c++) {
        int kb = c * 32;
        const float* src = (c < 4) ? X : AGG;
        const float4* sp = (const float4*)(src + crow_s * DD + (kb & 127)) + half * 4;
        const uint4* wp = (const uint4*)(Bw + srow * 256 + kb + half * 16);
        stage_chunk(sAh, sAl, sB, off, sp, wp);
        __syncthreads();
        chunk_compute(acc, aHi, aLo, aB, wm, wn, lane);
        __syncthreads();
    }

    // epilogue
#pragma unroll
    for (int mt = 0; mt < 2; mt++) {
        int r0 = blk + wm * 32 + mt * 16 + (lane >> 2);
        int r1 = r0 + 8;
        float s0 = 1.f, s1 = 1.f;
        if (WRITE_XN) {
            s0 = rsqrtf((float)deg[r0 < M ? r0 : M - 1]);
            s1 = rsqrtf((float)deg[r1 < M ? r1 : M - 1]);
        }
#pragma unroll
        for (int nt = 0; nt < 8; nt++) {
            int cc = wn * 64 + nt * 8 + (lane & 3) * 2;
            float2 bv = *(const float2*)(bias + cc);
            float v0 = acc[mt][nt][0] + bv.x;
            float v1 = acc[mt][nt][1] + bv.y;
            float v2 = acc[mt][nt][2] + bv.x;
            float v3 = acc[mt][nt][3] + bv.y;
            if (RELU) {
                v0 = fmaxf(v0, 0.f); v1 = fmaxf(v1, 0.f);
                v2 = fmaxf(v2, 0.f); v3 = fmaxf(v3, 0.f);
            }
            if (r0 < M) {
                *(float2*)(C + r0 * DD + cc) = make_float2(v0, v1);
                if (WRITE_XN) *(float2*)(XN + r0 * DD + cc) = make_float2(v0 * s0, v1 * s0);
            }
            if (r1 < M) {
                *(float2*)(C + r1 * DD + cc) = make_float2(v2, v3);
                if (WRITE_XN) *(float2*)(XN + r1 * DD + cc) = make_float2(v2 * s1, v3 * s1);
            }
        }
    }
}

// ---- HMMA link predictor, K=128, fused relu(z@Wa+ba)@Wb+bb ----
__global__ void __launch_bounds__(256, 2) k_mlinkpred(
    const float* __restrict__ H, const int* __restrict__ pairs,
    const __half* __restrict__ Bw,
    const float* __restrict__ ba, const float* __restrict__ Wb,
    const float* __restrict__ bb, float* __restrict__ out)
{
    __shared__ __align__(16) uint8_t sAh[128 * RS];
    __shared__ __align__(16) uint8_t sAl[128 * RS];
    __shared__ __align__(16) uint8_t sB[128 * RS];
    __shared__ float sacc[128];
    int tid = threadIdx.x;
    int lane = tid & 31, wid = tid >> 5;
    int wm = wid & 3, wn = wid >> 2;
    int blk = blockIdx.x * 128;

    if (tid < 128) sacc[tid] = 0.f;

    float acc[2][8][4];
#pragma unroll
    for (int mt = 0; mt < 2; mt++)
#pragma unroll
        for (int nt = 0; nt < 8; nt++)
#pragma unroll
            for (int i = 0; i < 4; i++) acc[mt][nt][i] = 0.f;

    int srow = tid >> 1, half = tid & 1;
    int grow_s = blk + srow;
    int crow_s = grow_s < NP ? grow_s : NP - 1;
    int ia = pairs[2 * crow_s];
    int ib = pairs[2 * crow_s + 1];
    int off = srow * RS + half * 32;

    uint32_t aHi = smem_u32(sAh), aLo = smem_u32(sAl), aB = smem_u32(sB);

    for (int c = 0; c < 4; c++) {
        int kb = c * 32;
        const float4* pa = (const float4*)(H + ia * DD + kb) + half * 4;
        const float4* pb = (const float4*)(H + ib * DD + kb) + half * 4;
        float4 pv[4];
#pragma unroll
        for (int i = 0; i < 4; i++) {
            float4 x = pa[i], y = pb[i];
            pv[i] = make_float4(x.x * y.x, x.y * y.y, x.z * y.z, x.w * y.w);
        }
        const uint4* wp = (const uint4*)(Bw + srow * 128 + kb + half * 16);
        stage_chunk(sAh, sAl, sB, off, pv, wp);
        __syncthreads();
        chunk_compute(acc, aHi, aLo, aB, wm, wn, lane);
        __syncthreads();
    }

    // epilogue: per-row sum of relu(acc + ba[c]) * Wb[c]
#pragma unroll
    for (int mt = 0; mt < 2; mt++) {
        int lr0 = wm * 32 + mt * 16 + (lane >> 2);
        float p0 = 0.f, p1 = 0.f;
#pragma unroll
        for (int nt = 0; nt < 8; nt++) {
            int cc = wn * 64 + nt * 8 + (lane & 3) * 2;
            float2 bav = *(const float2*)(ba + cc);
            float2 wbv = *(const float2*)(Wb + cc);
            p0 += fmaxf(acc[mt][nt][0] + bav.x, 0.f) * wbv.x
                + fmaxf(acc[mt][nt][1] + bav.y, 0.f) * wbv.y;
            p1 += fmaxf(acc[mt][nt][2] + bav.x, 0.f) * wbv.x
                + fmaxf(acc[mt][nt][3] + bav.y, 0.f) * wbv.y;
        }
        p0 += __shfl_xor_sync(0xffffffffu, p0, 1);
        p0 += __shfl_xor_sync(0xffffffffu, p0, 2);
        p1 += __shfl_xor_sync(0xffffffffu, p1, 1);
        p1 += __shfl_xor_sync(0xffffffffu, p1, 2);
        if ((lane & 3) == 0) {
            atomicAdd(&sacc[lr0], p0);
            atomicAdd(&sacc[lr0 + 8], p1);
        }
    }
    __syncthreads();
    if (tid < 128) {
        int row = blk + tid;
        if (row < NP) out[row] = sacc[tid] + bb[0];
    }
}

// ---------------------------------------------------------------------------
extern "C" void kernel_launch(void* const* d_in, const int* in_sizes, int n_in,
                              void* d_out, int out_size) {
    const int*   node_ids  = (const int*)d_in[0];
    const int*   senders   = (const int*)d_in[1];
    const int*   receivers = (const int*)d_in[2];
    const int*   pairs     = (const int*)d_in[3];
    const float* emb       = (const float*)d_in[4];
    const float* W1        = (const float*)d_in[5];
    const float* b1        = (const float*)d_in[6];
    const float* W2        = (const float*)d_in[7];
    const float* b2        = (const float*)d_in[8];
    const float* Wa        = (const float*)d_in[9];
    const float* ba        = (const float*)d_in[10];
    const float* Wb        = (const float*)d_in[11];
    const float* bb        = (const float*)d_in[12];
    float* out = (float*)d_out;

    float *x, *h, *ag, *xn;
    int* degs;
    __half *w1t, *w2t, *wat;
    cudaGetSymbolAddress((void**)&x,  g_x);
    cudaGetSymbolAddress((void**)&h,  g_h);
    cudaGetSymbolAddress((void**)&ag, g_agg);
    cudaGetSymbolAddress((void**)&xn, g_xnorm);
    cudaGetSymbolAddress((void**)&degs, g_deg_s);
    cudaGetSymbolAddress((void**)&w1t, g_w1t);
    cudaGetSymbolAddress((void**)&w2t, g_w2t);
    cudaGetSymbolAddress((void**)&wat, g_wat);

    const int vb = (NG4 + 255) / 256;   // 12500

    // 1) prep  2) count+scan  3) scatter+gather  4) aggregate (profiled)
    k_prep_all<<<(NN + 255) / 256, 256>>>(W1, W2, Wa);
    k_count_scan<<<2048, 256>>>(senders, receivers);
    k_scatter_gather<<<(NG4 + NE + 255) / 256, 256>>>(senders, receivers, node_ids, emb);
    k_aggregate<<<vb, 256>>>();

    // layer 1: x -> h (relu); epilogue also writes xnorm for layer-2 aggregate
    k_mgemm_layer<true, true><<<(NN + 127) / 128, 256>>>(
        x, ag, w1t, b1, h, xn, degs, NN);

    // layer 2: h -> x (no relu)
    k_aggregate<<<vb, 256>>>();
    k_mgemm_layer<false, false><<<(NN + 127) / 128, 256>>>(
        h, ag, w2t, b2, x, nullptr, degs, NN);

    // link predictor
    k_mlinkpred<<<(NP + 127) / 128, 256>>>(
        x, pairs, wat, ba, Wb, bb, out);
}